// round 2
// baseline (speedup 1.0000x reference)
#include <cuda_runtime.h>

// Problem constants: B=32, S1=14, S2=14, NC=2, DC=16, F=32, I=8
#define NROWS   200704      // B*S1*S2*NC*DC
#define DE      32          // NC*DC (rows repeat weights with period 32)
#define HALF    51380224    // NROWS * F * I  (elements per output tensor)

__device__ float g_maxWt[DE * 8];   // max over f of W_t[de, f, i]

__device__ __forceinline__ float ex2a(float x) {
    float y; asm("ex2.approx.ftz.f32 %0, %1;" : "=f"(y) : "f"(x)); return y;
}
__device__ __forceinline__ float rcpa(float x) {
    float y; asm("rcp.approx.ftz.f32 %0, %1;" : "=f"(y) : "f"(x)); return y;
}

// Tiny prep: maxWt[de*8+i] = max_f W_t[de*256 + f*8 + i]   (one block, 256 thr)
__global__ void mhsa_prep(const float* __restrict__ Wt) {
    int t = threadIdx.x;            // 0..255
    int de = t >> 3, i = t & 7;
    const float* p = Wt + de * 256 + i;
    float m = p[0];
    #pragma unroll
    for (int f = 1; f < 32; ++f) m = fmaxf(m, p[f * 8]);
    g_maxWt[t] = m;
}

__global__ void __launch_bounds__(256, 8)
mhsa_main(const float* __restrict__ U,
          const float* __restrict__ Wt,
          const float* __restrict__ Wa,
          float* __restrict__ outC,
          float* __restrict__ outUI)
{
    const int warp = (blockIdx.x * blockDim.x + threadIdx.x) >> 5;
    const int lane = threadIdx.x & 31;
    if (warp >= NROWS) return;

    const int row = warp;
    const int de  = row & (DE - 1);

    // ---- load U row: lane l owns f = l; then grab the two f's this lane needs
    const float u_mine = U[row * 32 + lane];
    const int f_lo = lane >> 1;                 // f for slot-lo (all 4 components)
    const float u_lo = __shfl_sync(0xffffffffu, u_mine, f_lo);
    const float u_hi = __shfl_sync(0xffffffffu, u_mine, f_lo + 16);

    // ---- weights (L1-resident, same (f*8+i) layout as outputs)
    const float4* wa4 = (const float4*)(Wa + de * 256);
    const float4* wt4 = (const float4*)(Wt + de * 256);
    const float4 waL = wa4[lane];
    const float4 waH = wa4[lane + 32];
    const float4 wtL = wt4[lane];
    const float4 wtH = wt4[lane + 32];

    // ---- U_hat_I = u * W_affine
    float4 uiL, uiH;
    uiL.x = u_lo * waL.x; uiL.y = u_lo * waL.y; uiL.z = u_lo * waL.z; uiL.w = u_lo * waL.w;
    uiH.x = u_hi * waH.x; uiH.y = u_hi * waH.y; uiH.z = u_hi * waH.z; uiH.w = u_hi * waH.w;

    float4* oUI = (float4*)(outUI + (size_t)row * 256);
    oUI[lane]      = uiL;
    oUI[lane + 32] = uiH;

    // ---- diag[i] = sum_f ui^2 / 4  (butterfly over same-parity lanes)
    float4 sq;
    sq.x = fmaf(uiL.x, uiL.x, uiH.x * uiH.x);
    sq.y = fmaf(uiL.y, uiL.y, uiH.y * uiH.y);
    sq.z = fmaf(uiL.z, uiL.z, uiH.z * uiH.z);
    sq.w = fmaf(uiL.w, uiL.w, uiH.w * uiH.w);
    #pragma unroll
    for (int m = 2; m <= 16; m <<= 1) {
        sq.x += __shfl_xor_sync(0xffffffffu, sq.x, m);
        sq.y += __shfl_xor_sync(0xffffffffu, sq.y, m);
        sq.z += __shfl_xor_sync(0xffffffffu, sq.z, m);
        sq.w += __shfl_xor_sync(0xffffffffu, sq.w, m);
    }

    // ds = diag * log2e  (fold /4 and log2e); diag >= 0 so row-max = ds * maxWt
    const float SC = 0.25f * 1.4426950408889634f;
    float4 ds;
    ds.x = sq.x * SC; ds.y = sq.y * SC; ds.z = sq.z * SC; ds.w = sq.w * SC;

    const float4 mw = *(const float4*)(g_maxWt + de * 8 + (lane & 1) * 4);
    float4 mx;
    mx.x = ds.x * mw.x; mx.y = ds.y * mw.y; mx.z = ds.z * mw.z; mx.w = ds.w * mw.w;

    float4 eL, eH;
    eL.x = ex2a(fmaf(ds.x, wtL.x, -mx.x));
    eL.y = ex2a(fmaf(ds.y, wtL.y, -mx.y));
    eL.z = ex2a(fmaf(ds.z, wtL.z, -mx.z));
    eL.w = ex2a(fmaf(ds.w, wtL.w, -mx.w));
    eH.x = ex2a(fmaf(ds.x, wtH.x, -mx.x));
    eH.y = ex2a(fmaf(ds.y, wtH.y, -mx.y));
    eH.z = ex2a(fmaf(ds.z, wtH.z, -mx.z));
    eH.w = ex2a(fmaf(ds.w, wtH.w, -mx.w));

    float4 s;
    s.x = eL.x + eH.x; s.y = eL.y + eH.y; s.z = eL.z + eH.z; s.w = eL.w + eH.w;
    #pragma unroll
    for (int m = 2; m <= 16; m <<= 1) {
        s.x += __shfl_xor_sync(0xffffffffu, s.x, m);
        s.y += __shfl_xor_sync(0xffffffffu, s.y, m);
        s.z += __shfl_xor_sync(0xffffffffu, s.z, m);
        s.w += __shfl_xor_sync(0xffffffffu, s.w, m);
    }

    float4 inv;
    inv.x = rcpa(s.x); inv.y = rcpa(s.y); inv.z = rcpa(s.z); inv.w = rcpa(s.w);

    float4 cL, cH;
    cL.x = eL.x * inv.x; cL.y = eL.y * inv.y; cL.z = eL.z * inv.z; cL.w = eL.w * inv.w;
    cH.x = eH.x * inv.x; cH.y = eH.y * inv.y; cH.z = eH.z * inv.z; cH.w = eH.w * inv.w;

    float4* oC = (float4*)(outC + (size_t)row * 256);
    oC[lane]      = cL;
    oC[lane + 32] = cH;
}

extern "C" void kernel_launch(void* const* d_in, const int* in_sizes, int n_in,
                              void* d_out, int out_size)
{
    const float* U  = (const float*)d_in[0];   // U_hat    (6,422,528)
    const float* Wt = (const float*)d_in[1];   // W_t      (8,192)
    const float* Wa = (const float*)d_in[2];   // W_affine (8,192)
    float* outC  = (float*)d_out;              // C first (return order)
    float* outUI = (float*)d_out + HALF;       // then U_hat_I

    mhsa_prep<<<1, 256>>>(Wt);
    const int warps_per_block = 8;             // 256 threads
    const int blocks = NROWS / warps_per_block; // 25088
    mhsa_main<<<blocks, 256>>>(U, Wt, Wa, outC, outUI);
}

// round 3
// speedup vs baseline: 1.0004x; 1.0004x over previous
#include <cuda_runtime.h>

// Problem constants: B=32, S1=14, S2=14, NC=2, DC=16, F=32, I=8
#define NROWS   200704      // B*S1*S2*NC*DC
#define DE      32          // NC*DC (rows repeat weights with period 32)
#define HALF    51380224    // NROWS * F * I  (elements per output tensor)

__device__ __forceinline__ float ex2a(float x) {
    float y; asm("ex2.approx.ftz.f32 %0, %1;" : "=f"(y) : "f"(x)); return y;
}
__device__ __forceinline__ float rcpa(float x) {
    float y; asm("rcp.approx.ftz.f32 %0, %1;" : "=f"(y) : "f"(x)); return y;
}

__global__ void __launch_bounds__(256, 8)
mhsa_main(const float* __restrict__ U,
          const float* __restrict__ Wt,
          const float* __restrict__ Wa,
          float* __restrict__ outC,
          float* __restrict__ outUI)
{
    const int warp = (blockIdx.x * blockDim.x + threadIdx.x) >> 5;
    const int lane = threadIdx.x & 31;
    if (warp >= NROWS) return;

    const int row = warp;
    const int de  = row & (DE - 1);

    // ---- load U row: lane l owns f = l; then grab the two f's this lane needs
    const float u_mine = U[row * 32 + lane];
    const int f_lo = lane >> 1;                 // f for slot-lo (all 4 components)
    const float u_lo = __shfl_sync(0xffffffffu, u_mine, f_lo);
    const float u_hi = __shfl_sync(0xffffffffu, u_mine, f_lo + 16);

    // ---- weights (L1-resident, same (f*8+i) layout as outputs)
    const float4* wa4 = (const float4*)(Wa + de * 256);
    const float4* wt4 = (const float4*)(Wt + de * 256);
    const float4 waL = wa4[lane];
    const float4 waH = wa4[lane + 32];
    const float4 wtL = wt4[lane];
    const float4 wtH = wt4[lane + 32];

    // ---- U_hat_I = u * W_affine
    float4 uiL, uiH;
    uiL.x = u_lo * waL.x; uiL.y = u_lo * waL.y; uiL.z = u_lo * waL.z; uiL.w = u_lo * waL.w;
    uiH.x = u_hi * waH.x; uiH.y = u_hi * waH.y; uiH.z = u_hi * waH.z; uiH.w = u_hi * waH.w;

    float4* oUI = (float4*)(outUI + (size_t)row * 256);
    __stcs(oUI + lane,      uiL);
    __stcs(oUI + lane + 32, uiH);

    // ---- diag[i] = sum_f ui^2 / 4, and mw[i] = max_f Wt[de,f,i]
    //      both via parity-preserving butterflies (xor 2/4/8/16)
    float4 sq, wm;
    sq.x = fmaf(uiL.x, uiL.x, uiH.x * uiH.x);
    sq.y = fmaf(uiL.y, uiL.y, uiH.y * uiH.y);
    sq.z = fmaf(uiL.z, uiL.z, uiH.z * uiH.z);
    sq.w = fmaf(uiL.w, uiL.w, uiH.w * uiH.w);
    wm.x = fmaxf(wtL.x, wtH.x);
    wm.y = fmaxf(wtL.y, wtH.y);
    wm.z = fmaxf(wtL.z, wtH.z);
    wm.w = fmaxf(wtL.w, wtH.w);
    #pragma unroll
    for (int m = 2; m <= 16; m <<= 1) {
        sq.x += __shfl_xor_sync(0xffffffffu, sq.x, m);
        sq.y += __shfl_xor_sync(0xffffffffu, sq.y, m);
        sq.z += __shfl_xor_sync(0xffffffffu, sq.z, m);
        sq.w += __shfl_xor_sync(0xffffffffu, sq.w, m);
        wm.x = fmaxf(wm.x, __shfl_xor_sync(0xffffffffu, wm.x, m));
        wm.y = fmaxf(wm.y, __shfl_xor_sync(0xffffffffu, wm.y, m));
        wm.z = fmaxf(wm.z, __shfl_xor_sync(0xffffffffu, wm.z, m));
        wm.w = fmaxf(wm.w, __shfl_xor_sync(0xffffffffu, wm.w, m));
    }

    // ds = diag * log2e  (fold /4 and log2e); diag >= 0 so row-max = ds * mw
    const float SC = 0.25f * 1.4426950408889634f;
    float4 ds;
    ds.x = sq.x * SC; ds.y = sq.y * SC; ds.z = sq.z * SC; ds.w = sq.w * SC;

    float4 mx;
    mx.x = ds.x * wm.x; mx.y = ds.y * wm.y; mx.z = ds.z * wm.z; mx.w = ds.w * wm.w;

    float4 eL, eH;
    eL.x = ex2a(fmaf(ds.x, wtL.x, -mx.x));
    eL.y = ex2a(fmaf(ds.y, wtL.y, -mx.y));
    eL.z = ex2a(fmaf(ds.z, wtL.z, -mx.z));
    eL.w = ex2a(fmaf(ds.w, wtL.w, -mx.w));
    eH.x = ex2a(fmaf(ds.x, wtH.x, -mx.x));
    eH.y = ex2a(fmaf(ds.y, wtH.y, -mx.y));
    eH.z = ex2a(fmaf(ds.z, wtH.z, -mx.z));
    eH.w = ex2a(fmaf(ds.w, wtH.w, -mx.w));

    float4 s;
    s.x = eL.x + eH.x; s.y = eL.y + eH.y; s.z = eL.z + eH.z; s.w = eL.w + eH.w;
    #pragma unroll
    for (int m = 2; m <= 16; m <<= 1) {
        s.x += __shfl_xor_sync(0xffffffffu, s.x, m);
        s.y += __shfl_xor_sync(0xffffffffu, s.y, m);
        s.z += __shfl_xor_sync(0xffffffffu, s.z, m);
        s.w += __shfl_xor_sync(0xffffffffu, s.w, m);
    }

    float4 inv;
    inv.x = rcpa(s.x); inv.y = rcpa(s.y); inv.z = rcpa(s.z); inv.w = rcpa(s.w);

    float4 cL, cH;
    cL.x = eL.x * inv.x; cL.y = eL.y * inv.y; cL.z = eL.z * inv.z; cL.w = eL.w * inv.w;
    cH.x = eH.x * inv.x; cH.y = eH.y * inv.y; cH.z = eH.z * inv.z; cH.w = eH.w * inv.w;

    float4* oC = (float4*)(outC + (size_t)row * 256);
    __stcs(oC + lane,      cL);
    __stcs(oC + lane + 32, cH);
}

extern "C" void kernel_launch(void* const* d_in, const int* in_sizes, int n_in,
                              void* d_out, int out_size)
{
    const float* U  = (const float*)d_in[0];   // U_hat    (6,422,528)
    const float* Wt = (const float*)d_in[1];   // W_t      (8,192)
    const float* Wa = (const float*)d_in[2];   // W_affine (8,192)
    float* outC  = (float*)d_out;              // C first (return order)
    float* outUI = (float*)d_out + HALF;       // then U_hat_I

    const int warps_per_block = 8;              // 256 threads
    const int blocks = NROWS / warps_per_block; // 25088
    mhsa_main<<<blocks, 256>>>(U, Wt, Wa, outC, outUI);
}